// round 14
// baseline (speedup 1.0000x reference)
#include <cuda_runtime.h>
#include <math.h>

#define B 128

__device__ float g_h1[B * 1024];
__device__ float g_h2[B * 512];
__device__ float g_h3[B * 256];

__device__ __forceinline__ float ex2f(float x) {
    float y;
    asm("ex2.approx.f32 %0, %1;" : "=f"(y) : "f"(x));
    return y;
}

// identity on [0,1], slope 0.1 outside
__device__ __forceinline__ float leaky_clamp01(float w) {
    float r = w;
    if (w < 0.0f)      r = 0.1f * w;
    else if (w > 1.0f) r = 1.0f + 0.1f * (w - 1.0f);
    return r;
}

__device__ __forceinline__ float tau_scale(const float* taup, float tau_floor) {
    float ta  = __ldg(taup);
    float tau = tau_floor + (ta >= 0.0f ? ta : 0.05f * ta);  // leaky_relu
    return tau * 1.4426950408889634f;                        // tau * log2(e)
}

// ============================================================================
// Chunked kernel (big layers), OPT=1: thread owns ONE (b,o) output.
// Small blocks, ~1024 blocks per launch -> ~6.9 blocks/SM, ~1% MUFU imbalance.
//   out[b,o] = 1 - (sum e^arg * arg)/(cs * sum e^arg), arg = cs*h[b,i]*aw[o,i]
// CAT: layer-0 mode, h is x[B][IN/2], staged as concat(x, 1-x).
// ============================================================================
template <int IN, int BT, int OT, int KC, bool CAT>
__global__ __launch_bounds__(BT * OT) void layer_chunked(
    const float* __restrict__ h, const float* __restrict__ W,
    const float* __restrict__ taup, float tau_floor,
    float* __restrict__ out, int out_dim) {
    constexpr int T   = BT * OT;
    constexpr int KCP = KC + 4;
    __shared__ float ch[BT * KCP];
    __shared__ float aw[OT * KCP];

    const int tid   = threadIdx.x;
    const int obase = blockIdx.x * OT;
    const int bbase = blockIdx.y * BT;
    const int b     = tid % BT;
    const int o     = tid / BT;

    const float cs = tau_scale(taup, tau_floor);

    float num = 0.f, den = 0.f;

    for (int k0 = 0; k0 < IN; k0 += KC) {
        if (k0) __syncthreads();
        {   // stage activations (fused concat(x,1-x) for layer 0)
            const bool inv  = CAT && (k0 >= IN / 2);
            const float sc  = inv ? -cs : cs;
            const float off = inv ?  cs : 0.0f;
            const int hk0   = CAT ? (k0 & (IN / 2 - 1)) : k0;
            const int hstr  = CAT ? (IN / 2) : IN;
            #pragma unroll
            for (int i = tid; i < BT * (KC / 4); i += T) {
                int bb = i / (KC / 4), kv = i - bb * (KC / 4);
                float4 v = *(const float4*)&h[(bbase + bb) * hstr + hk0 + kv * 4];
                float4 r;
                r.x = fmaf(v.x, sc, off); r.y = fmaf(v.y, sc, off);
                r.z = fmaf(v.z, sc, off); r.w = fmaf(v.w, sc, off);
                *(float4*)&ch[bb * KCP + kv * 4] = r;
            }
        }
        #pragma unroll
        for (int i = tid; i < OT * (KC / 4); i += T) {
            int oo = i / (KC / 4), kv = i - oo * (KC / 4);
            float4 v = *(const float4*)&W[(obase + oo) * IN + k0 + kv * 4];
            float4 r;
            r.x = leaky_clamp01(v.x); r.y = leaky_clamp01(v.y);
            r.z = leaky_clamp01(v.z); r.w = leaky_clamp01(v.w);
            *(float4*)&aw[oo * KCP + kv * 4] = r;
        }
        __syncthreads();

        const float* cp = &ch[b * KCP];
        const float* ap = &aw[o * KCP];
        #pragma unroll 8
        for (int k = 0; k < KC; k += 4) {
            float4 c = *(const float4*)&cp[k];
            float4 a = *(const float4*)&ap[k];
            float z;
            z = c.x * a.x; { float e = ex2f(z); den += e; num = fmaf(e, z, num); }
            z = c.y * a.y; { float e = ex2f(z); den += e; num = fmaf(e, z, num); }
            z = c.z * a.z; { float e = ex2f(z); den += e; num = fmaf(e, z, num); }
            z = c.w * a.w; { float e = ex2f(z); den += e; num = fmaf(e, z, num); }
        }
    }

    out[(bbase + b) * out_dim + obase + o] = 1.0f - (num / den) / cs;
}

// ============================================================================
// Split kernel (small layers). Whole input staged once; S threads per output,
// each covering IN/S of K; partials (num, den additive) reduced via smem.
// Shapes chosen for ~1024 blocks -> even per-SM load.
// ============================================================================
template <int IN, int BT, int OT, int S>
__global__ __launch_bounds__(BT * OT * S) void layer_split(
    const float* __restrict__ h, const float* __restrict__ W,
    const float* __restrict__ taup, float tau_floor,
    float* __restrict__ out, int out_dim) {
    constexpr int T   = BT * OT * S;
    constexpr int G   = BT * OT;
    constexpr int KR  = IN / S;
    constexpr int INP = IN + 4;
    static_assert((G & (G - 1)) == 0, "G must be power of two");
    __shared__ float ch[BT * INP];
    __shared__ float aw[OT * INP];
    __shared__ float2 rpart[T];

    const int tid   = threadIdx.x;
    const int obase = blockIdx.x * OT;
    const int bbase = blockIdx.y * BT;
    const int idx   = tid & (G - 1);
    const int s     = tid / G;
    const int b     = idx % BT;
    const int o     = idx / BT;

    const float cs = tau_scale(taup, tau_floor);

    #pragma unroll
    for (int i = tid; i < BT * (IN / 4); i += T) {
        int bb = i / (IN / 4), kv = i - bb * (IN / 4);
        float4 v = *(const float4*)&h[(bbase + bb) * IN + kv * 4];
        float4 r; r.x = v.x * cs; r.y = v.y * cs; r.z = v.z * cs; r.w = v.w * cs;
        *(float4*)&ch[bb * INP + kv * 4] = r;
    }
    #pragma unroll
    for (int i = tid; i < OT * (IN / 4); i += T) {
        int oo = i / (IN / 4), kv = i - oo * (IN / 4);
        float4 v = *(const float4*)&W[(obase + oo) * IN + kv * 4];
        float4 r;
        r.x = leaky_clamp01(v.x); r.y = leaky_clamp01(v.y);
        r.z = leaky_clamp01(v.z); r.w = leaky_clamp01(v.w);
        *(float4*)&aw[oo * INP + kv * 4] = r;
    }
    __syncthreads();

    float num = 0.0f, den = 0.0f;
    const float* cp = &ch[b * INP + s * KR];
    const float* ap = &aw[o * INP + s * KR];
    #pragma unroll 4
    for (int k = 0; k < KR; k += 4) {
        float4 c = *(const float4*)&cp[k];
        float4 a = *(const float4*)&ap[k];
        float z;
        z = c.x * a.x; { float e = ex2f(z); den += e; num = fmaf(e, z, num); }
        z = c.y * a.y; { float e = ex2f(z); den += e; num = fmaf(e, z, num); }
        z = c.z * a.z; { float e = ex2f(z); den += e; num = fmaf(e, z, num); }
        z = c.w * a.w; { float e = ex2f(z); den += e; num = fmaf(e, z, num); }
    }

    rpart[tid] = make_float2(num, den);
    __syncthreads();
    if (s == 0) {
        #pragma unroll
        for (int ss = 1; ss < S; ss++) {
            float2 p = rpart[idx + ss * G];
            num += p.x;
            den += p.y;
        }
        out[(bbase + b) * out_dim + obase + o] = 1.0f - (num / den) / cs;
    }
}

extern "C" void kernel_launch(void* const* d_in, const int* in_sizes, int n_in,
                              void* d_out, int out_size) {
    // metadata order: x, W0, tau0, W1, tau1, W2, tau2, W3, tau3
    const float* x  = (const float*)d_in[0];
    const float* W0 = (const float*)d_in[1];
    const float* t0 = (const float*)d_in[2];
    const float* W1 = (const float*)d_in[3];
    const float* t1 = (const float*)d_in[4];
    const float* W2 = (const float*)d_in[5];
    const float* t2 = (const float*)d_in[6];
    const float* W3 = (const float*)d_in[7];
    const float* t3 = (const float*)d_in[8];
    float* out = (float*)d_out;

    float *h1, *h2, *h3;
    cudaGetSymbolAddress((void**)&h1, g_h1);
    cudaGetSymbolAddress((void**)&h2, g_h2);
    cudaGetSymbolAddress((void**)&h3, g_h3);

    // tau_floor = log(in-1) + log(0.95/0.05)
    const float L19 = 2.9444389791664403f;
    const float tf0 = logf(1023.0f) + L19;
    const float tf1 = logf(1023.0f) + L19;
    const float tf2 = logf(511.0f)  + L19;
    const float tf3 = logf(255.0f)  + L19;

    // L0: 1024->1024, fused concat. 1024 blocks x 128 thr (6.9 blk/SM).
    layer_chunked<1024, 8, 16, 256, true>
        <<<dim3(1024 / 16, B / 8), 128>>>(x, W0, t0, tf0, h1, 1024);
    // L1: 1024->512. 1024 blocks x 64 thr (6.9 blk/SM).
    layer_chunked<1024, 8, 8, 256, false>
        <<<dim3(512 / 8, B / 8), 64>>>(h1, W1, t1, tf1, h2, 512);
    // L2: 512->256, 4-way split. 1024 blocks x 128 thr (6.9 blk/SM).
    layer_split<512, 4, 8, 4>
        <<<dim3(256 / 8, B / 4), 128>>>(h2, W2, t2, tf2, h3, 256);
    // L3: 256->128, 4-way split. 1024 blocks x 64 thr (6.9 blk/SM).
    layer_split<256, 2, 8, 4>
        <<<dim3(128 / 8, B / 2), 64>>>(h3, W3, t3, tf3, out, 128);
}